// round 5
// baseline (speedup 1.0000x reference)
#include <cuda_runtime.h>
#include <math.h>

#define NB 8
#define NC 512
#define NL 4096
#define NH 8
#define ND 64
#define NO 1536
#define LN_EPS 1e-5f
#define ATT_SCALE 0.125f
#define NSPLIT 8

// Scratch (device globals: allocation-free per harness rules)
__device__ float g_xn[(size_t)NB * NC * NL];            // 64 MB : layernormed x
__device__ float g_qkv[(size_t)NB * NO * NL];           // 192 MB: qkv projection
__device__ float g_ctxp[(size_t)NSPLIT * NB * NH * ND * ND]; // context partials
__device__ float g_weff[(size_t)NB * NC * NC];          // 8 MB : fused w_out @ blockdiag(ctx^T)

// ---------------------------------------------------------------------------
// K1: LayerNorm over channel dim (axis C) per (b, l)
// ---------------------------------------------------------------------------
__global__ void ln_kernel(const float* __restrict__ x,
                          const float* __restrict__ gamma,
                          const float* __restrict__ beta) {
    int b = blockIdx.y;
    int l = blockIdx.x * 128 + threadIdx.x;
    const float* xp = x + (size_t)b * NC * NL + l;
    float s = 0.f, s2 = 0.f;
    #pragma unroll 8
    for (int c = 0; c < NC; c++) {
        float v = xp[(size_t)c * NL];
        s += v;
        s2 += v * v;
    }
    float mean = s * (1.f / NC);
    float var = fmaf(-mean, mean, s2 * (1.f / NC));
    float inv = rsqrtf(var + LN_EPS);
    float* op = g_xn + (size_t)b * NC * NL + l;
    #pragma unroll 8
    for (int c = 0; c < NC; c++) {
        float v = xp[(size_t)c * NL];
        op[(size_t)c * NL] = (v - mean) * inv * gamma[c] + beta[c];
    }
}

// ---------------------------------------------------------------------------
// K2 / K6: 128x128x8 double-buffered fp32 GEMM (K = 512, N = 4096)
// MODE 0: qkv = w_qkv(1536x512) @ xn[b]                  -> g_qkv
// MODE 1: out = weff[b](512x512) @ q[b] + b_out + xn[b]  -> d_out
// One __syncthreads per K-tile; LDS.128 fragment loads.
// ---------------------------------------------------------------------------
template <int MODE>
__global__ void __launch_bounds__(256) gemm_kernel(const float* __restrict__ Aext,
                                                   const float* __restrict__ bias,
                                                   float* __restrict__ outext) {
    const int K = NC;   // 512
    const int N = NL;   // 4096
    int bz = blockIdx.z;

    const float* Ab;
    const float* Bb;
    float* Cb;
    if (MODE == 0) {
        Ab = Aext;                                   // shared weights
        Bb = g_xn + (size_t)bz * NC * NL;
        Cb = g_qkv + (size_t)bz * NO * NL;
    } else {
        Ab = g_weff + (size_t)bz * NC * NC;          // per-batch effective weights
        Bb = g_qkv + (size_t)bz * NO * NL;           // q occupies rows [0, 512)
        Cb = outext + (size_t)bz * NC * NL;
    }

    __shared__ float As[2][8][128];
    __shared__ float Bs[2][8][128];

    int tid = threadIdx.x;
    int tr = tid >> 4, tc = tid & 15;
    int bm = blockIdx.y * 128, bn = blockIdx.x * 128;
    int arow = tid >> 1, acol = (tid & 1) * 4;
    int brow = tid >> 5, bcol = (tid & 31) * 4;

    const float* Aptr = Ab + (size_t)(bm + arow) * K + acol;
    const float* Bptr = Bb + (size_t)brow * N + bn + bcol;

    float acc[8][8] = {};

    // Preload tile 0
    {
        float4 av = *(const float4*)(Aptr);
        float4 bv = *(const float4*)(Bptr);
        As[0][acol + 0][arow] = av.x;
        As[0][acol + 1][arow] = av.y;
        As[0][acol + 2][arow] = av.z;
        As[0][acol + 3][arow] = av.w;
        *(float4*)&Bs[0][brow][bcol] = bv;
    }
    __syncthreads();

    int buf = 0;
    for (int k0 = 0; k0 < K; k0 += 8) {
        // Prefetch next tile from gmem into registers (overlaps with compute)
        float4 av, bv;
        bool more = (k0 + 8) < K;
        if (more) {
            av = *(const float4*)(Aptr + k0 + 8);
            bv = *(const float4*)(Bptr + (size_t)(k0 + 8) * N);
        }

        #pragma unroll
        for (int kk = 0; kk < 8; kk++) {
            float4 a0 = *(const float4*)&As[buf][kk][tr * 8];
            float4 a1 = *(const float4*)&As[buf][kk][tr * 8 + 4];
            float4 b0 = *(const float4*)&Bs[buf][kk][tc * 8];
            float4 b1 = *(const float4*)&Bs[buf][kk][tc * 8 + 4];
            float am[8] = {a0.x, a0.y, a0.z, a0.w, a1.x, a1.y, a1.z, a1.w};
            float bm2[8] = {b0.x, b0.y, b0.z, b0.w, b1.x, b1.y, b1.z, b1.w};
            #pragma unroll
            for (int i = 0; i < 8; i++)
                #pragma unroll
                for (int j = 0; j < 8; j++)
                    acc[i][j] = fmaf(am[i], bm2[j], acc[i][j]);
        }

        if (more) {
            int nb = buf ^ 1;
            As[nb][acol + 0][arow] = av.x;
            As[nb][acol + 1][arow] = av.y;
            As[nb][acol + 2][arow] = av.z;
            As[nb][acol + 3][arow] = av.w;
            *(float4*)&Bs[nb][brow][bcol] = bv;
            __syncthreads();
        }
        buf ^= 1;
    }

    #pragma unroll
    for (int i = 0; i < 8; i++) {
        int row = bm + tr * 8 + i;
        float badd = (MODE == 1) ? bias[row] : 0.f;
        #pragma unroll
        for (int j0 = 0; j0 < 8; j0 += 4) {
            int col = bn + tc * 8 + j0;
            float4 o;
            o.x = acc[i][j0 + 0] + badd;
            o.y = acc[i][j0 + 1] + badd;
            o.z = acc[i][j0 + 2] + badd;
            o.w = acc[i][j0 + 3] + badd;
            if (MODE == 1) {
                const float4 r = *(const float4*)(g_xn + ((size_t)bz * NC + row) * NL + col);
                o.x += r.x; o.y += r.y; o.z += r.z; o.w += r.w;
            }
            *(float4*)(Cb + (size_t)row * NL + col) = o;
        }
    }
}

// ---------------------------------------------------------------------------
// K3: softmax over L (axis=-1) on the k section (rows 512..1023 per batch)
// ---------------------------------------------------------------------------
__global__ void __launch_bounds__(256) softmax_kernel() {
    int r = blockIdx.x;              // 0 .. NB*512-1
    int b = r >> 9, hd = r & 511;
    float* p = g_qkv + (size_t)b * NO * NL + (size_t)(NC + hd) * NL;
    int t = threadIdx.x;

    float v[16];
    float mx = -1e30f;
    #pragma unroll
    for (int i = 0; i < 16; i++) {
        v[i] = p[t + i * 256];
        mx = fmaxf(mx, v[i]);
    }
    __shared__ float sr[8];
    #pragma unroll
    for (int o = 16; o; o >>= 1) mx = fmaxf(mx, __shfl_xor_sync(0xffffffffu, mx, o));
    if ((t & 31) == 0) sr[t >> 5] = mx;
    __syncthreads();
    float m = sr[0];
    #pragma unroll
    for (int i = 1; i < 8; i++) m = fmaxf(m, sr[i]);

    float s = 0.f;
    #pragma unroll
    for (int i = 0; i < 16; i++) {
        v[i] = __expf(v[i] - m);
        s += v[i];
    }
    #pragma unroll
    for (int o = 16; o; o >>= 1) s += __shfl_xor_sync(0xffffffffu, s, o);
    __syncthreads();
    if ((t & 31) == 0) sr[t >> 5] = s;
    __syncthreads();
    float tot = 0.f;
    #pragma unroll
    for (int i = 0; i < 8; i++) tot += sr[i];
    float inv = 1.f / tot;
    #pragma unroll
    for (int i = 0; i < 16; i++) p[t + i * 256] = v[i] * inv;
}

// ---------------------------------------------------------------------------
// K4: context partials  ctx[b,h,d,e] = SCALE * sum_n k[d,n]*v[e,n]
// N split 8 ways, deterministic (no atomics).
// ---------------------------------------------------------------------------
__global__ void __launch_bounds__(256) context_kernel() {
    int part = blockIdx.x;
    int bh = blockIdx.y;
    int b = bh >> 3, h = bh & 7;
    const float* kp = g_qkv + (size_t)b * NO * NL + (size_t)(NC + h * ND) * NL;
    const float* vp = g_qkv + (size_t)b * NO * NL + (size_t)(2 * NC + h * ND) * NL;

    __shared__ float Ks[64][65];  // [n][d] transposed, padded
    __shared__ float Vs[64][65];  // [n][e]

    int tid = threadIdx.x;
    int tr = tid >> 4, tc = tid & 15;
    float acc[4][4] = {};
    int nbase = part * (NL / NSPLIT);

    for (int n0 = 0; n0 < NL / NSPLIT; n0 += 64) {
        for (int i = tid; i < 4096; i += 256) {
            int d = i >> 6, n = i & 63;
            Ks[n][d] = kp[(size_t)d * NL + nbase + n0 + n];
            Vs[n][d] = vp[(size_t)d * NL + nbase + n0 + n];
        }
        __syncthreads();
        #pragma unroll 4
        for (int n = 0; n < 64; n++) {
            float a[4], w[4];
            #pragma unroll
            for (int i = 0; i < 4; i++) a[i] = Ks[n][tr * 4 + i];
            #pragma unroll
            for (int j = 0; j < 4; j++) w[j] = Vs[n][tc * 4 + j];
            #pragma unroll
            for (int i = 0; i < 4; i++)
                #pragma unroll
                for (int j = 0; j < 4; j++)
                    acc[i][j] = fmaf(a[i], w[j], acc[i][j]);
        }
        __syncthreads();
    }

    float* cp = g_ctxp + ((size_t)part * (NB * NH) + bh) * (ND * ND);
    #pragma unroll
    for (int i = 0; i < 4; i++)
        #pragma unroll
        for (int j = 0; j < 4; j++)
            cp[(tr * 4 + i) * ND + tc * 4 + j] = acc[i][j] * ATT_SCALE;
}

// ---------------------------------------------------------------------------
// K5: Weff[b][o][h*64+d] = sum_e w_out[o][h*64+e] * ctx[b,h,d,e]
// ---------------------------------------------------------------------------
__global__ void __launch_bounds__(256) weff_kernel(const float* __restrict__ w_out) {
    int bh = blockIdx.x;
    int b = bh >> 3, h = bh & 7;
    __shared__ float cs[64][65];  // [d][e]
    int tid = threadIdx.x;

    for (int i = tid; i < 4096; i += 256) {
        float s = 0.f;
        #pragma unroll
        for (int p = 0; p < NSPLIT; p++)
            s += g_ctxp[((size_t)p * (NB * NH) + bh) * 4096 + i];
        cs[i >> 6][i & 63] = s;
    }
    __syncthreads();

    for (int i = tid; i < NC * ND; i += 256) {
        int o = i >> 6, d = i & 63;
        const float* wr = w_out + (size_t)o * NC + h * ND;
        float s = 0.f;
        #pragma unroll
        for (int e = 0; e < 64; e++) s = fmaf(wr[e], cs[d][e], s);
        g_weff[((size_t)b * NC + o) * NC + h * ND + d] = s;
    }
}

// ---------------------------------------------------------------------------
// Launch pipeline (graph-capturable: kernel launches only, ordered on stream 0)
// Inputs (metadata order): x, g, b, w_qkv, w_out, b_out
// ---------------------------------------------------------------------------
extern "C" void kernel_launch(void* const* d_in, const int* in_sizes, int n_in,
                              void* d_out, int out_size) {
    const float* x     = (const float*)d_in[0];
    const float* gamma = (const float*)d_in[1];
    const float* beta  = (const float*)d_in[2];
    const float* w_qkv = (const float*)d_in[3];
    const float* w_out = (const float*)d_in[4];
    const float* b_out = (const float*)d_in[5];
    float* out = (float*)d_out;

    ln_kernel<<<dim3(NL / 128, NB), 128>>>(x, gamma, beta);
    gemm_kernel<0><<<dim3(NL / 128, NO / 128, NB), 256>>>(w_qkv, nullptr, nullptr);
    softmax_kernel<<<NB * NC, 256>>>();
    context_kernel<<<dim3(NSPLIT, NB * NH), 256>>>();
    weff_kernel<<<NB * NH, 256>>>(w_out);
    gemm_kernel<1><<<dim3(NL / 128, NC / 128, NB), 256>>>(nullptr, b_out, out);
}

// round 15
// speedup vs baseline: 1.6658x; 1.6658x over previous
#include <cuda_runtime.h>
#include <cuda_bf16.h>
#include <cstdint>
#include <stdint.h>
#include <math.h>

#define NB 8
#define NC 512
#define NL 4096
#define NH 8
#define ND 64
#define NO 1536
#define LN_EPS 1e-5f
#define ATT_SCALE 0.125f
#define NSPLIT 8

// ---------------- scratch (device globals; allocation-free) ----------------
__device__ float g_xn[(size_t)NB * NC * NL];                     // 64 MB fp32 (residual)
__device__ __align__(16) __nv_bfloat16 g_xnh[(size_t)NB * NC * NL];  // 32 MB hi
__device__ __align__(16) __nv_bfloat16 g_xnl[(size_t)NB * NC * NL];  // 32 MB lo
__device__ float g_qkv[(size_t)NB * NO * NL];                    // 192 MB fp32
__device__ __align__(16) __nv_bfloat16 g_qh[(size_t)NB * NC * NL];   // q hi
__device__ __align__(16) __nv_bfloat16 g_ql[(size_t)NB * NC * NL];   // q lo
__device__ __align__(16) __nv_bfloat16 g_wqh[(size_t)NO * NC];
__device__ __align__(16) __nv_bfloat16 g_wql[(size_t)NO * NC];
__device__ float g_ctxp[(size_t)NSPLIT * NB * NH * ND * ND];
__device__ __align__(16) __nv_bfloat16 g_wfh[(size_t)NB * NC * NC];
__device__ __align__(16) __nv_bfloat16 g_wfl[(size_t)NB * NC * NC];

__device__ __forceinline__ void bf16split(float v, __nv_bfloat16& h, __nv_bfloat16& l) {
    h = __float2bfloat16(v);
    l = __float2bfloat16(v - __bfloat162float(h));
}

// ---------------------------------------------------------------------------
// K1: LayerNorm over C per (b,l); writes fp32 + bf16 hi/lo copies
// ---------------------------------------------------------------------------
__global__ void ln_kernel(const float* __restrict__ x,
                          const float* __restrict__ gamma,
                          const float* __restrict__ beta) {
    int b = blockIdx.y;
    int l = blockIdx.x * 128 + threadIdx.x;
    const float* xp = x + (size_t)b * NC * NL + l;
    float s = 0.f, s2 = 0.f;
    #pragma unroll 8
    for (int c = 0; c < NC; c++) {
        float v = xp[(size_t)c * NL];
        s += v; s2 += v * v;
    }
    float mean = s * (1.f / NC);
    float var = fmaf(-mean, mean, s2 * (1.f / NC));
    float inv = rsqrtf(var + LN_EPS);
    size_t base = (size_t)b * NC * NL + l;
    #pragma unroll 8
    for (int c = 0; c < NC; c++) {
        float v = xp[(size_t)c * NL];
        float o = (v - mean) * inv * gamma[c] + beta[c];
        g_xn[base + (size_t)c * NL] = o;
        __nv_bfloat16 h, lo;
        bf16split(o, h, lo);
        g_xnh[base + (size_t)c * NL] = h;
        g_xnl[base + (size_t)c * NL] = lo;
    }
}

// ---------------------------------------------------------------------------
// K1b: w_qkv -> bf16 hi/lo
// ---------------------------------------------------------------------------
__global__ void wconv_kernel(const float* __restrict__ w) {
    int i = blockIdx.x * 256 + threadIdx.x;
    if (i < NO * NC) {
        __nv_bfloat16 h, l;
        bf16split(w[i], h, l);
        g_wqh[i] = h; g_wql[i] = l;
    }
}

// ---------------------------------------------------------------------------
// MMA GEMM: C[M][4096] = A[M][512] @ B[512][4096], bf16 hi/lo split (3 MMAs),
// fp32 accumulate.  mma.sync.m16n8k16 + ldmatrix.  Block 128x128, 8 warps.
// MODE 0: A=w_qkv(hi/lo), B=xn(hi/lo)  -> g_qkv fp32 (+ q rows re-split to bf16)
// MODE 1: A=weff[b](hi/lo), B=q(hi/lo) -> out = acc + bias + xn
// ---------------------------------------------------------------------------
#define BM 128
#define BN 128
#define BK 16
#define SA 24      // A smem row stride (elems) — conflict-free ldmatrix
#define SB 136     // B smem row stride (elems)

__device__ __forceinline__ void ldsm4(unsigned* r, unsigned addr) {
    asm volatile("ldmatrix.sync.aligned.m8n8.x4.shared.b16 {%0,%1,%2,%3}, [%4];"
                 : "=r"(r[0]), "=r"(r[1]), "=r"(r[2]), "=r"(r[3]) : "r"(addr));
}
__device__ __forceinline__ void ldsm2t(unsigned* r, unsigned addr) {
    asm volatile("ldmatrix.sync.aligned.m8n8.x2.trans.shared.b16 {%0,%1}, [%2];"
                 : "=r"(r[0]), "=r"(r[1]) : "r"(addr));
}
__device__ __forceinline__ void mma16816(float* c, const unsigned* a, const unsigned* b) {
    asm volatile(
        "mma.sync.aligned.m16n8k16.row.col.f32.bf16.bf16.f32 "
        "{%0,%1,%2,%3},{%4,%5,%6,%7},{%8,%9},{%0,%1,%2,%3};"
        : "+f"(c[0]), "+f"(c[1]), "+f"(c[2]), "+f"(c[3])
        : "r"(a[0]), "r"(a[1]), "r"(a[2]), "r"(a[3]), "r"(b[0]), "r"(b[1]));
}

template <int MODE>
__global__ void __launch_bounds__(256, 1) mma_gemm(const float* __restrict__ bias,
                                                   float* __restrict__ Cg) {
    const int K = NC, N = NL;
    int z = blockIdx.z;

    const __nv_bfloat16 *Ah_g, *Al_g, *Bh_g, *Bl_g;
    float* C;
    if (MODE == 0) {
        Ah_g = g_wqh;                      Al_g = g_wql;
        Bh_g = g_xnh + (size_t)z * NC * NL; Bl_g = g_xnl + (size_t)z * NC * NL;
        C = g_qkv + (size_t)z * NO * NL;
    } else {
        Ah_g = g_wfh + (size_t)z * NC * NC; Al_g = g_wfl + (size_t)z * NC * NC;
        Bh_g = g_qh + (size_t)z * NC * NL;  Bl_g = g_ql + (size_t)z * NC * NL;
        C = Cg + (size_t)z * NC * NL;
    }

    __shared__ __align__(16) __nv_bfloat16 Ash[2][BM * SA];
    __shared__ __align__(16) __nv_bfloat16 Asl[2][BM * SA];
    __shared__ __align__(16) __nv_bfloat16 Bsh[2][BK * SB];
    __shared__ __align__(16) __nv_bfloat16 Bsl[2][BK * SB];

    int t = threadIdx.x;
    int lane = t & 31, wid = t >> 5;
    int wm = wid >> 2, wn = wid & 3;           // warp grid 2x4, warp tile 64x32
    int bm = blockIdx.y * BM, bn = blockIdx.x * BN;

    // global->smem load mapping (one uint4 per array per thread per tile)
    int ar = t >> 1, ac = (t & 1) * 8;         // A: 128 rows x 16 k
    int br = t >> 4, bc = (t & 15) * 8;        // B: 16 rows  x 128 n
    const __nv_bfloat16* Aph = Ah_g + (size_t)(bm + ar) * K + ac;
    const __nv_bfloat16* Apl = Al_g + (size_t)(bm + ar) * K + ac;
    const __nv_bfloat16* Bph = Bh_g + (size_t)br * N + bn + bc;
    const __nv_bfloat16* Bpl = Bl_g + (size_t)br * N + bn + bc;
    int a_st = ar * SA + ac;
    int b_st = br * SB + bc;

    // ldmatrix lane offsets (bytes), fixed across k-steps
    unsigned ahb[2] = { (unsigned)__cvta_generic_to_shared(Ash[0]),
                        (unsigned)__cvta_generic_to_shared(Ash[1]) };
    unsigned alb[2] = { (unsigned)__cvta_generic_to_shared(Asl[0]),
                        (unsigned)__cvta_generic_to_shared(Asl[1]) };
    unsigned bhb[2] = { (unsigned)__cvta_generic_to_shared(Bsh[0]),
                        (unsigned)__cvta_generic_to_shared(Bsh[1]) };
    unsigned blb[2] = { (unsigned)__cvta_generic_to_shared(Bsl[0]),
                        (unsigned)__cvta_generic_to_shared(Bsl[1]) };
    unsigned offA[4], offB[4];
    #pragma unroll
    for (int i = 0; i < 4; i++) {
        int arow = wm * 64 + i * 16 + (lane & 15);
        int acol = (lane >> 4) * 8;
        offA[i] = (unsigned)((arow * SA + acol) * 2);
    }
    #pragma unroll
    for (int j = 0; j < 4; j++) {
        int brow = lane & 15;
        int bcol = wn * 32 + j * 8;
        offB[j] = (unsigned)((brow * SB + bcol) * 2);
    }

    float acc[4][4][4] = {};

    // preload tile 0
    {
        uint4 va = *(const uint4*)Aph;   uint4 vb = *(const uint4*)Apl;
        uint4 vc = *(const uint4*)Bph;   uint4 vd = *(const uint4*)Bpl;
        *(uint4*)&Ash[0][a_st] = va;  *(uint4*)&Asl[0][a_st] = vb;
        *(uint4*)&Bsh[0][b_st] = vc;  *(uint4*)&Bsl[0][b_st] = vd;
    }
    __syncthreads();

    int buf = 0;
    for (int k0 = 0; k0 < K; k0 += BK) {
        bool more = (k0 + BK) < K;
        uint4 pa, pb, pc, pd;
        if (more) {
            pa = *(const uint4*)(Aph + k0 + BK);
            pb = *(const uint4*)(Apl + k0 + BK);
            pc = *(const uint4*)(Bph + (size_t)(k0 + BK) * N);
            pd = *(const uint4*)(Bpl + (size_t)(k0 + BK) * N);
        }

        unsigned fah[4][4], fal[4][4], fbh[4][2], fbl[4][2];
        #pragma unroll
        for (int i = 0; i < 4; i++) {
            ldsm4(fah[i], ahb[buf] + offA[i]);
            ldsm4(fal[i], alb[buf] + offA[i]);
        }
        #pragma unroll
        for (int j = 0; j < 4; j++) {
            ldsm2t(fbh[j], bhb[buf] + offB[j]);
            ldsm2t(fbl[j], blb[buf] + offB[j]);
        }
        #pragma unroll
        for (int i = 0; i < 4; i++)
            #pragma unroll
            for (int j = 0; j < 4; j++) {
                mma16816(acc[i][j], fah[i], fbh[j]);
                mma16816(acc[i][j], fah[i], fbl[j]);
                mma16816(acc[i][j], fal[i], fbh[j]);
            }

        if (more) {
            int nb = buf ^ 1;
            *(uint4*)&Ash[nb][a_st] = pa;  *(uint4*)&Asl[nb][a_st] = pb;
            *(uint4*)&Bsh[nb][b_st] = pc;  *(uint4*)&Bsl[nb][b_st] = pd;
            __syncthreads();
        }
        buf ^= 1;
    }

    // epilogue
    bool isq = (MODE == 0) && (bm < NC);   // q tiles are whole 128-row tiles
    #pragma unroll
    for (int i = 0; i < 4; i++) {
        #pragma unroll
        for (int j = 0; j < 4; j++) {
            int row = bm + wm * 64 + i * 16 + (lane >> 2);
            int col = bn + wn * 32 + j * 8 + ((lane & 3) << 1);
            float v0 = acc[i][j][0], v1 = acc[i][j][1];
            float v2 = acc[i][j][2], v3 = acc[i][j][3];
            if (MODE == 1) {
                float b0 = bias[row], b1 = bias[row + 8];
                const float* xr0 = g_xn + ((size_t)z * NC + row) * NL + col;
                const float* xr1 = g_xn + ((size_t)z * NC + row + 8) * NL + col;
                v0 += b0 + xr0[0];  v1 += b0 + xr0[1];
                v2 += b1 + xr1[0]; v3 += b1 + xr1[1];
            }
            float2 p0 = {v0, v1}, p1 = {v2, v3};
            *(float2*)&C[(size_t)row * NL + col] = p0;
            *(float2*)&C[(size_t)(row + 8) * NL + col] = p1;
            if (isq) {
                __nv_bfloat16 h0, l0, h1, l1;
                size_t q0 = ((size_t)z * NC + row) * NL + col;
                size_t q1 = ((size_t)z * NC + row + 8) * NL + col;
                bf16split(v0, h0, l0); bf16split(v1, h1, l1);
                *(__nv_bfloat162*)&g_qh[q0] = __halves2bfloat162(h0, h1);
                *(__nv_bfloat162*)&g_ql[q0] = __halves2bfloat162(l0, l1);
                bf16split(v2, h0, l0); bf16split(v3, h1, l1);
                *(__nv_bfloat162*)&g_qh[q1] = __halves2bfloat162(h0, h1);
                *(__nv_bfloat162*)&g_ql[q1] = __halves2bfloat162(l0, l1);
            }
        }
    }
}

// ---------------------------------------------------------------------------
// K3: softmax over L on k rows (fp32, unchanged)
// ---------------------------------------------------------------------------
__global__ void __launch_bounds__(256) softmax_kernel() {
    int r = blockIdx.x;
    int b = r >> 9, hd = r & 511;
    float* p = g_qkv + (size_t)b * NO * NL + (size_t)(NC + hd) * NL;
    int t = threadIdx.x;

    float v[16];
    float mx = -1e30f;
    #pragma unroll
    for (int i = 0; i < 16; i++) { v[i] = p[t + i * 256]; mx = fmaxf(mx, v[i]); }
    __shared__ float sr[8];
    #pragma unroll
    for (int o = 16; o; o >>= 1) mx = fmaxf(mx, __shfl_xor_sync(0xffffffffu, mx, o));
    if ((t & 31) == 0) sr[t >> 5] = mx;
    __syncthreads();
    float m = sr[0];
    #pragma unroll
    for (int i = 1; i < 8; i++) m = fmaxf(m, sr[i]);

    float s = 0.f;
    #pragma unroll
    for (int i = 0; i < 16; i++) { v[i] = __expf(v[i] - m); s += v[i]; }
    #pragma unroll
    for (int o = 16; o; o >>= 1) s += __shfl_xor_sync(0xffffffffu, s, o);
    __syncthreads();
    if ((t & 31) == 0) sr[t >> 5] = s;
    __syncthreads();
    float tot = 0.f;
    #pragma unroll
    for (int i = 0; i < 8; i++) tot += sr[i];
    float inv = 1.f / tot;
    #pragma unroll
    for (int i = 0; i < 16; i++) p[t + i * 256] = v[i] * inv;
}

// ---------------------------------------------------------------------------
// K4: context partials (fp32, unchanged)
// ---------------------------------------------------------------------------
__global__ void __launch_bounds__(256) context_kernel() {
    int part = blockIdx.x;
    int bh = blockIdx.y;
    int b = bh >> 3, h = bh & 7;
    const float* kp = g_qkv + (size_t)b * NO * NL + (size_t)(NC + h * ND) * NL;
    const float* vp = g_qkv + (size_t)b * NO * NL + (size_t)(2 * NC + h * ND) * NL;

    __shared__ float Ks[64][65];
    __shared__ float Vs[64][65];

    int tid = threadIdx.x;
    int tr = tid >> 4, tc = tid & 15;
    float acc[4][4] = {};
    int nbase = part * (NL / NSPLIT);

    for (int n0 = 0; n0 < NL / NSPLIT; n0 += 64) {
        for (int i = tid; i < 4096; i += 256) {
            int d = i >> 6, n = i & 63;
            Ks[n][d] = kp[(size_t)d * NL + nbase + n0 + n];
            Vs[n][d] = vp[(size_t)d * NL + nbase + n0 + n];
        }
        __syncthreads();
        #pragma unroll 4
        for (int n = 0; n < 64; n++) {
            float a[4], w[4];
            #pragma unroll
            for (int i = 0; i < 4; i++) a[i] = Ks[n][tr * 4 + i];
            #pragma unroll
            for (int j = 0; j < 4; j++) w[j] = Vs[n][tc * 4 + j];
            #pragma unroll
            for (int i = 0; i < 4; i++)
                #pragma unroll
                for (int j = 0; j < 4; j++)
                    acc[i][j] = fmaf(a[i], w[j], acc[i][j]);
        }
        __syncthreads();
    }

    float* cp = g_ctxp + ((size_t)part * (NB * NH) + bh) * (ND * ND);
    #pragma unroll
    for (int i = 0; i < 4; i++)
        #pragma unroll
        for (int j = 0; j < 4; j++)
            cp[(tr * 4 + i) * ND + tc * 4 + j] = acc[i][j] * ATT_SCALE;
}

// ---------------------------------------------------------------------------
// K5: Weff = w_out @ blockdiag(ctx^T), output split to bf16 hi/lo
// ---------------------------------------------------------------------------
__global__ void __launch_bounds__(256) weff_kernel(const float* __restrict__ w_out) {
    int bh = blockIdx.x;
    int b = bh >> 3, hh = bh & 7;
    __shared__ float cs[64][65];
    int tid = threadIdx.x;

    for (int i = tid; i < 4096; i += 256) {
        float s = 0.f;
        #pragma unroll
        for (int p = 0; p < NSPLIT; p++)
            s += g_ctxp[((size_t)p * (NB * NH) + bh) * 4096 + i];
        cs[i >> 6][i & 63] = s;
    }
    __syncthreads();

    for (int i = tid; i < NC * ND; i += 256) {
        int o = i >> 6, d = i & 63;
        const float* wr = w_out + (size_t)o * NC + hh * ND;
        float s = 0.f;
        #pragma unroll
        for (int e = 0; e < 64; e++) s = fmaf(wr[e], cs[d][e], s);
        size_t idx = ((size_t)b * NC + o) * NC + hh * ND + d;
        __nv_bfloat16 h, l;
        bf16split(s, h, l);
        g_wfh[idx] = h; g_wfl[idx] = l;
    }
}

// ---------------------------------------------------------------------------
// Launch pipeline
// ---------------------------------------------------------------------------
extern "C" void kernel_launch(void* const* d_in, const int* in_sizes, int n_in,
                              void* d_out, int out_size) {
    const float* x     = (const float*)d_in[0];
    const float* gamma = (const float*)d_in[1];
    const float* beta  = (const float*)d_in[2];
    const float* w_qkv = (const float*)d_in[3];
    const float* w_out = (const float*)d_in[4];
    const float* b_out = (const float*)d_in[5];
    float* out = (float*)d_out;

    ln_kernel<<<dim3(NL / 128, NB), 128>>>(x, gamma, beta);
    wconv_kernel<<<(NO * NC + 255) / 256, 256>>>(w_qkv);
    mma_gemm<0><<<dim3(NL / BN, NO / BM, NB), 256>>>(nullptr, nullptr);
    softmax_kernel<<<NB * NC, 256>>>();
    context_kernel<<<dim3(NSPLIT, NB * NH), 256>>>();
    weff_kernel<<<NB * NH, 256>>>(w_out);
    mma_gemm<1><<<dim3(NL / BN, NC / BM, NB), 256>>>(b_out, out);
}